// round 9
// baseline (speedup 1.0000x reference)
#include <cuda_runtime.h>

// RelationAwareAttention: B=1, H=8, L=512, D=64
// out = concat(attn_sum[1,8,512,64], p_attn[1,8,512,512]) as float32.
//
// Decomposition (removes all k/v re-reads from the streaming kernel):
//   A: S1 = Q K^T per head (k read once)            -> g_s1 scratch
//   B: score=(S1 + q.rk)/8, softmax, p_attn,
//      R_i = sum_j p_j rv_ij -> out_attn            (pure rk/rv stream)
//   C: out_attn += P V (v read once, P from L2)

#define L_SEQ 512
#define D_DIM 64
#define H_HEADS 8

__device__ float g_s1[(size_t)H_HEADS * L_SEQ * L_SEQ];   // 8.4 MB scratch

// ---------------- Kernel A: S1 = Q K^T ----------------
__global__ __launch_bounds__(256)
void qk_kernel(const float* __restrict__ q, const float* __restrict__ k)
{
    const int jt = blockIdx.x, it = blockIdx.y, h = blockIdx.z;
    const int i0 = it << 6, j0 = jt << 6;
    __shared__ float sq[64][68];
    __shared__ float sk[64][68];
    const int tid = threadIdx.x;

    for (int idx = tid; idx < 64 * 16; idx += 256) {
        const int row = idx >> 4, c4 = (idx & 15) << 2;
        const float4 a = *reinterpret_cast<const float4*>(
            q + ((size_t)h * L_SEQ + i0 + row) * D_DIM + c4);
        sq[row][c4] = a.x; sq[row][c4 + 1] = a.y; sq[row][c4 + 2] = a.z; sq[row][c4 + 3] = a.w;
        const float4 b = *reinterpret_cast<const float4*>(
            k + ((size_t)h * L_SEQ + j0 + row) * D_DIM + c4);
        sk[row][c4] = b.x; sk[row][c4 + 1] = b.y; sk[row][c4 + 2] = b.z; sk[row][c4 + 3] = b.w;
    }
    __syncthreads();

    const int ty = tid >> 4, tx = tid & 15;
    float acc[4][4] = {};
    #pragma unroll 8
    for (int kk = 0; kk < 64; ++kk) {
        float a[4], b[4];
        #pragma unroll
        for (int r = 0; r < 4; ++r) a[r] = sq[4 * ty + r][kk];
        #pragma unroll
        for (int c = 0; c < 4; ++c) b[c] = sk[4 * tx + c][kk];
        #pragma unroll
        for (int r = 0; r < 4; ++r)
            #pragma unroll
            for (int c = 0; c < 4; ++c) acc[r][c] += a[r] * b[c];
    }
    #pragma unroll
    for (int r = 0; r < 4; ++r) {
        const float4 o = make_float4(acc[r][0], acc[r][1], acc[r][2], acc[r][3]);
        *reinterpret_cast<float4*>(
            g_s1 + ((size_t)h * L_SEQ + i0 + 4 * ty + r) * L_SEQ + j0 + 4 * tx) = o;
    }
}

// ---------------- Kernel B: relation stream + softmax ----------------
__global__ __launch_bounds__(256)
void rel_attn_kernel(const float* __restrict__ q_g,
                     const float* __restrict__ rk_g,
                     const float* __restrict__ rv_g,
                     const int*   __restrict__ mask_g,
                     float* __restrict__ out_attn,
                     float* __restrict__ out_p)
{
    const int i    = blockIdx.x;
    const int h    = blockIdx.y;
    const int tid  = threadIdx.x;
    const int warp = tid >> 5;
    const int lane = tid & 31;
    const int half = lane >> 4;
    const int hl   = lane & 15;

    __shared__ float  s_score[L_SEQ];
    __shared__ float  s_s1[L_SEQ];
    __shared__ int    s_mask[L_SEQ];
    __shared__ float  s_red[8];
    __shared__ float4 s_acc[16][16];

    const float* q   = q_g  + ((size_t)h * L_SEQ + i) * D_DIM;
    const float* rk  = rk_g + (((size_t)h * L_SEQ + i) * L_SEQ) * D_DIM;
    const int*   mrow = mask_g + (size_t)i * L_SEQ;           // broadcast over h (B=1)
    const float* s1row = g_s1 + ((size_t)h * L_SEQ + i) * L_SEQ;

    // Preload S1 row + mask row (coalesced, L2-resident).
    s_s1[tid]         = s1row[tid];
    s_s1[tid + 256]   = s1row[tid + 256];
    s_mask[tid]       = mrow[tid];
    s_mask[tid + 256] = mrow[tid + 256];
    __syncthreads();

    // Phase 1: score[j] = (S1[j] + q . rk[i,j]) / 8, masked.
    const float4 q4 = *reinterpret_cast<const float4*>(q + 4 * hl);

    #pragma unroll 4
    for (int jj = 0; jj < 32; ++jj) {
        const int j = (warp << 6) + (jj << 1) + half;
        const float4 rr = *reinterpret_cast<const float4*>(rk + (size_t)j * D_DIM + 4 * hl);
        float p = q4.x * rr.x + q4.y * rr.y + q4.z * rr.z + q4.w * rr.w;
        p += __shfl_xor_sync(0xffffffffu, p, 8);
        p += __shfl_xor_sync(0xffffffffu, p, 4);
        p += __shfl_xor_sync(0xffffffffu, p, 2);
        p += __shfl_xor_sync(0xffffffffu, p, 1);
        if (hl == 0) {
            float s = (s_s1[j] + p) * 0.125f;      // 1/sqrt(64)
            if (s_mask[j] == 0) s = -1e9f;
            s_score[j] = s;
        }
    }
    __syncthreads();

    // Phase 2: softmax over j (thread owns tid, tid+256).
    float v0 = s_score[tid];
    float v1 = s_score[tid + 256];

    float m = fmaxf(v0, v1);
    #pragma unroll
    for (int o = 16; o > 0; o >>= 1)
        m = fmaxf(m, __shfl_xor_sync(0xffffffffu, m, o));
    if (lane == 0) s_red[warp] = m;
    __syncthreads();
    if (tid == 0) {
        float mm = s_red[0];
        #pragma unroll
        for (int w = 1; w < 8; ++w) mm = fmaxf(mm, s_red[w]);
        s_red[0] = mm;
    }
    __syncthreads();
    m = s_red[0];
    __syncthreads();

    const float e0 = __expf(v0 - m);
    const float e1 = __expf(v1 - m);
    float ssum = e0 + e1;
    #pragma unroll
    for (int o = 16; o > 0; o >>= 1)
        ssum += __shfl_xor_sync(0xffffffffu, ssum, o);
    if (lane == 0) s_red[warp] = ssum;
    __syncthreads();
    if (tid == 0) {
        float tot = s_red[0];
        #pragma unroll
        for (int w = 1; w < 8; ++w) tot += s_red[w];
        s_red[0] = tot;
    }
    __syncthreads();
    const float inv = 1.0f / s_red[0];

    const float p0 = e0 * inv;
    const float p1 = e1 * inv;
    s_score[tid]       = p0;
    s_score[tid + 256] = p1;

    const size_t pbase = ((size_t)h * L_SEQ + i) * L_SEQ;
    out_p[pbase + tid]       = p0;
    out_p[pbase + tid + 256] = p1;
    __syncthreads();

    // Phase 3: R_i[d] = sum_j p[j] * rv[i,j,d]   (the P.V part is kernel C)
    const int gid = (warp << 1) + half;
    const float* rv = rv_g + (((size_t)h * L_SEQ + i) * L_SEQ) * D_DIM;

    float4 acc = make_float4(0.f, 0.f, 0.f, 0.f);
    #pragma unroll 4
    for (int j = gid; j < L_SEQ; j += 16) {
        const float  pj = s_score[j];
        const float4 rr = *reinterpret_cast<const float4*>(rv + (size_t)j * D_DIM + 4 * hl);
        acc.x += pj * rr.x;
        acc.y += pj * rr.y;
        acc.z += pj * rr.z;
        acc.w += pj * rr.w;
    }
    s_acc[gid][hl] = acc;
    __syncthreads();

    if (tid < 16) {
        float4 r = make_float4(0.f, 0.f, 0.f, 0.f);
        #pragma unroll
        for (int gg = 0; gg < 16; ++gg) {
            const float4 a = s_acc[gg][tid];
            r.x += a.x; r.y += a.y; r.z += a.z; r.w += a.w;
        }
        float4* oa = reinterpret_cast<float4*>(out_attn + ((size_t)h * L_SEQ + i) * D_DIM);
        oa[tid] = r;
    }
}

// ---------------- Kernel C: out_attn += P V ----------------
__global__ __launch_bounds__(256)
void pv_kernel(const float* __restrict__ p,
               const float* __restrict__ v,
               float* __restrict__ out_attn)
{
    const int it = blockIdx.x, h = blockIdx.y;
    const int i0 = it << 6;
    __shared__ float sp[64][68];
    __shared__ float sv[64][68];
    const int tid = threadIdx.x;
    const int ty = tid >> 4, tx = tid & 15;

    float acc[4][4] = {};
    for (int jc = 0; jc < 8; ++jc) {
        for (int idx = tid; idx < 64 * 16; idx += 256) {
            const int row = idx >> 4, c4 = (idx & 15) << 2;
            const float4 a = *reinterpret_cast<const float4*>(
                p + ((size_t)h * L_SEQ + i0 + row) * L_SEQ + (jc << 6) + c4);
            sp[row][c4] = a.x; sp[row][c4 + 1] = a.y; sp[row][c4 + 2] = a.z; sp[row][c4 + 3] = a.w;
            const float4 b = *reinterpret_cast<const float4*>(
                v + ((size_t)h * L_SEQ + (jc << 6) + row) * D_DIM + c4);
            sv[row][c4] = b.x; sv[row][c4 + 1] = b.y; sv[row][c4 + 2] = b.z; sv[row][c4 + 3] = b.w;
        }
        __syncthreads();
        #pragma unroll 8
        for (int kk = 0; kk < 64; ++kk) {
            float a[4], b[4];
            #pragma unroll
            for (int r = 0; r < 4; ++r) a[r] = sp[4 * ty + r][kk];
            #pragma unroll
            for (int c = 0; c < 4; ++c) b[c] = sv[kk][4 * tx + c];
            #pragma unroll
            for (int r = 0; r < 4; ++r)
                #pragma unroll
                for (int c = 0; c < 4; ++c) acc[r][c] += a[r] * b[c];
        }
        __syncthreads();
    }
    #pragma unroll
    for (int r = 0; r < 4; ++r) {
        float4* dst = reinterpret_cast<float4*>(
            out_attn + ((size_t)h * L_SEQ + i0 + 4 * ty + r) * D_DIM + 4 * tx);
        float4 o = *dst;                      // R term from kernel B
        o.x += acc[r][0]; o.y += acc[r][1]; o.z += acc[r][2]; o.w += acc[r][3];
        *dst = o;
    }
}

extern "C" void kernel_launch(void* const* d_in, const int* in_sizes, int n_in,
                              void* d_out, int out_size)
{
    const float* q    = (const float*)d_in[0];
    const float* k    = (const float*)d_in[1];
    const float* v    = (const float*)d_in[2];
    const float* rk   = (const float*)d_in[3];
    const float* rv   = (const float*)d_in[4];
    const int*   mask = (const int*)  d_in[5];

    float* out      = (float*)d_out;
    float* out_attn = out;                                        // [1,8,512,64]
    float* out_p    = out + (size_t)H_HEADS * L_SEQ * D_DIM;      // [1,8,512,512]

    qk_kernel<<<dim3(8, 8, 8), 256>>>(q, k);
    rel_attn_kernel<<<dim3(L_SEQ, H_HEADS), 256>>>(q, rk, rv, mask, out_attn, out_p);
    pv_kernel<<<dim3(8, H_HEADS), 256>>>(out_p, v, out_attn);
}

// round 13
// speedup vs baseline: 1.3227x; 1.3227x over previous
#include <cuda_runtime.h>

// RelationAwareAttention: B=1, H=8, L=512, D=64
// out = concat(attn_sum[1,8,512,64], p_attn[1,8,512,512]) as float32.
//
// A: S1 = Q K^T per head (fast tiled GEMM, 1024 CTAs)  -> g_s1 scratch
// B: score = (S1[j] + q.rk_ij)/8, softmax, p_attn,
//    out_i = sum_j p_j (v_j + rv_ij)   (v via cache, rk/rv streamed evict-first)

#define L_SEQ 512
#define D_DIM 64
#define H_HEADS 8

__device__ float g_s1[(size_t)H_HEADS * L_SEQ * L_SEQ];   // 8.4 MB scratch

// ---------------- Kernel A: S1 = Q K^T ----------------
// Output tile 32(i) x 64(j), K=64. Transposed smem, 1024 CTAs.
// skT row stride = 68 floats (272 B = 16*17): every float4 read is 16B-aligned.
__global__ __launch_bounds__(256)
void qk_kernel(const float* __restrict__ q, const float* __restrict__ k)
{
    const int jt = blockIdx.x;            // 8
    const int it = blockIdx.y;            // 16
    const int h  = blockIdx.z;            // 8
    const int i0 = it << 5, j0 = jt << 6;
    __shared__ float sqT[64][33];         // [kk][i-local], scalar reads only
    __shared__ float skT[64][68];         // [kk][j-local], float4 reads (aligned)
    const int tid = threadIdx.x;

    // load q tile 32x64, store transposed
    for (int idx = tid; idx < 32 * 16; idx += 256) {
        const int row = idx >> 4, c4 = (idx & 15) << 2;
        const float4 a = *reinterpret_cast<const float4*>(
            q + ((size_t)h * L_SEQ + i0 + row) * D_DIM + c4);
        sqT[c4 + 0][row] = a.x; sqT[c4 + 1][row] = a.y;
        sqT[c4 + 2][row] = a.z; sqT[c4 + 3][row] = a.w;
    }
    // load k tile 64x64, store transposed
    for (int idx = tid; idx < 64 * 16; idx += 256) {
        const int row = idx >> 4, c4 = (idx & 15) << 2;
        const float4 b = *reinterpret_cast<const float4*>(
            k + ((size_t)h * L_SEQ + j0 + row) * D_DIM + c4);
        skT[c4 + 0][row] = b.x; skT[c4 + 1][row] = b.y;
        skT[c4 + 2][row] = b.z; skT[c4 + 3][row] = b.w;
    }
    __syncthreads();

    const int ty = tid >> 4, tx = tid & 15;   // 16 x 16
    float acc0[4] = {0.f, 0.f, 0.f, 0.f};
    float acc1[4] = {0.f, 0.f, 0.f, 0.f};
    #pragma unroll 16
    for (int kk = 0; kk < 64; ++kk) {
        const float a0 = sqT[kk][2 * ty];
        const float a1 = sqT[kk][2 * ty + 1];
        const float4 b = *reinterpret_cast<const float4*>(&skT[kk][4 * tx]);
        acc0[0] += a0 * b.x; acc0[1] += a0 * b.y; acc0[2] += a0 * b.z; acc0[3] += a0 * b.w;
        acc1[0] += a1 * b.x; acc1[1] += a1 * b.y; acc1[2] += a1 * b.z; acc1[3] += a1 * b.w;
    }

    float* dst = g_s1 + ((size_t)h * L_SEQ + i0 + 2 * ty) * L_SEQ + j0 + 4 * tx;
    *reinterpret_cast<float4*>(dst)         = make_float4(acc0[0], acc0[1], acc0[2], acc0[3]);
    *reinterpret_cast<float4*>(dst + L_SEQ) = make_float4(acc1[0], acc1[1], acc1[2], acc1[3]);
}

// ---------------- Kernel B: relation stream + softmax + fused PV ----------------
__global__ __launch_bounds__(256)
void rel_attn_kernel(const float* __restrict__ q_g,
                     const float* __restrict__ v_g,
                     const float* __restrict__ rk_g,
                     const float* __restrict__ rv_g,
                     const int*   __restrict__ mask_g,
                     float* __restrict__ out_attn,
                     float* __restrict__ out_p)
{
    const int i    = blockIdx.x;
    const int h    = blockIdx.y;
    const int tid  = threadIdx.x;
    const int warp = tid >> 5;
    const int lane = tid & 31;
    const int half = lane >> 4;
    const int hl   = lane & 15;

    __shared__ float  s_score[L_SEQ];
    __shared__ float  s_s1[L_SEQ];
    __shared__ int    s_mask[L_SEQ];
    __shared__ float  s_red[8];
    __shared__ float4 s_acc[16][16];

    const float* q     = q_g  + ((size_t)h * L_SEQ + i) * D_DIM;
    const float* rk    = rk_g + (((size_t)h * L_SEQ + i) * L_SEQ) * D_DIM;
    const int*   mrow  = mask_g + (size_t)i * L_SEQ;          // broadcast over h (B=1)
    const float* s1row = g_s1 + ((size_t)h * L_SEQ + i) * L_SEQ;

    // Preload S1 row (L2-resident) + mask row, coalesced.
    s_s1[tid]         = s1row[tid];
    s_s1[tid + 256]   = s1row[tid + 256];
    s_mask[tid]       = mrow[tid];
    s_mask[tid + 256] = mrow[tid + 256];
    __syncthreads();

    // Phase 1: score[j] = (S1[j] + q . rk[i,j]) / 8, masked.
    const float4 q4 = *reinterpret_cast<const float4*>(q + 4 * hl);

    #pragma unroll 8
    for (int jj = 0; jj < 32; ++jj) {
        const int j = (warp << 6) + (jj << 1) + half;
        const float4 rr = __ldcs(reinterpret_cast<const float4*>(rk + (size_t)j * D_DIM + 4 * hl));
        float p = q4.x * rr.x + q4.y * rr.y + q4.z * rr.z + q4.w * rr.w;
        p += __shfl_xor_sync(0xffffffffu, p, 8);
        p += __shfl_xor_sync(0xffffffffu, p, 4);
        p += __shfl_xor_sync(0xffffffffu, p, 2);
        p += __shfl_xor_sync(0xffffffffu, p, 1);
        if (hl == 0) {
            float s = (s_s1[j] + p) * 0.125f;      // 1/sqrt(64)
            if (s_mask[j] == 0) s = -1e9f;
            s_score[j] = s;
        }
    }
    __syncthreads();

    // Phase 2: softmax over j (thread owns tid, tid+256).
    float v0 = s_score[tid];
    float v1 = s_score[tid + 256];

    float m = fmaxf(v0, v1);
    #pragma unroll
    for (int o = 16; o > 0; o >>= 1)
        m = fmaxf(m, __shfl_xor_sync(0xffffffffu, m, o));
    if (lane == 0) s_red[warp] = m;
    __syncthreads();
    if (tid == 0) {
        float mm = s_red[0];
        #pragma unroll
        for (int w = 1; w < 8; ++w) mm = fmaxf(mm, s_red[w]);
        s_red[0] = mm;
    }
    __syncthreads();
    m = s_red[0];
    __syncthreads();

    const float e0 = __expf(v0 - m);
    const float e1 = __expf(v1 - m);
    float ssum = e0 + e1;
    #pragma unroll
    for (int o = 16; o > 0; o >>= 1)
        ssum += __shfl_xor_sync(0xffffffffu, ssum, o);
    if (lane == 0) s_red[warp] = ssum;
    __syncthreads();
    if (tid == 0) {
        float tot = s_red[0];
        #pragma unroll
        for (int w = 1; w < 8; ++w) tot += s_red[w];
        s_red[0] = tot;
    }
    __syncthreads();
    const float inv = 1.0f / s_red[0];

    const float p0 = e0 * inv;
    const float p1 = e1 * inv;
    s_score[tid]       = p0;
    s_score[tid + 256] = p1;

    const size_t pbase = ((size_t)h * L_SEQ + i) * L_SEQ;
    out_p[pbase + tid]       = p0;
    out_p[pbase + tid + 256] = p1;
    __syncthreads();

    // Phase 3: out_i[d] = sum_j p[j] * (v[j,d] + rv[i,j,d]).
    // v via default caching (head-major bid order keeps it hot), rv evict-first.
    const int gid = (warp << 1) + half;
    const float* vrow = v_g  + (size_t)h * L_SEQ * D_DIM;
    const float* rv   = rv_g + (((size_t)h * L_SEQ + i) * L_SEQ) * D_DIM;

    float4 acc = make_float4(0.f, 0.f, 0.f, 0.f);
    #pragma unroll 4
    for (int j = gid; j < L_SEQ; j += 16) {
        const float  pj  = s_score[j];
        const size_t off = (size_t)j * D_DIM + 4 * hl;
        const float4 vv  = *reinterpret_cast<const float4*>(vrow + off);
        const float4 rr  = __ldcs(reinterpret_cast<const float4*>(rv + off));
        acc.x += pj * (vv.x + rr.x);
        acc.y += pj * (vv.y + rr.y);
        acc.z += pj * (vv.z + rr.z);
        acc.w += pj * (vv.w + rr.w);
    }
    s_acc[gid][hl] = acc;
    __syncthreads();

    if (tid < 16) {
        float4 r = make_float4(0.f, 0.f, 0.f, 0.f);
        #pragma unroll
        for (int gg = 0; gg < 16; ++gg) {
            const float4 a = s_acc[gg][tid];
            r.x += a.x; r.y += a.y; r.z += a.z; r.w += a.w;
        }
        float4* oa = reinterpret_cast<float4*>(out_attn + ((size_t)h * L_SEQ + i) * D_DIM);
        oa[tid] = r;
    }
}

extern "C" void kernel_launch(void* const* d_in, const int* in_sizes, int n_in,
                              void* d_out, int out_size)
{
    const float* q    = (const float*)d_in[0];
    const float* k    = (const float*)d_in[1];
    const float* v    = (const float*)d_in[2];
    const float* rk   = (const float*)d_in[3];
    const float* rv   = (const float*)d_in[4];
    const int*   mask = (const int*)  d_in[5];

    float* out      = (float*)d_out;
    float* out_attn = out;                                        // [1,8,512,64]
    float* out_p    = out + (size_t)H_HEADS * L_SEQ * D_DIM;      // [1,8,512,512]

    qk_kernel<<<dim3(8, 16, 8), 256>>>(q, k);
    rel_attn_kernel<<<dim3(L_SEQ, H_HEADS), 256>>>(q, v, rk, rv, mask, out_attn, out_p);
}

// round 15
// speedup vs baseline: 1.3683x; 1.0345x over previous
#include <cuda_runtime.h>

// RelationAwareAttention: B=1, H=8, L=512, D=64
// out = concat(attn_sum[1,8,512,64], p_attn[1,8,512,512]) as float32.
//
// A: S1 = Q K^T per head — FFMA2 (fma.rn.f32x2) tiled GEMM, 512 CTAs
// B: score = (S1[j] + q.rk_ij)/8, softmax, p_attn,
//    out_i = sum_j p_j (v_j + rv_ij)   (v via cache, rk/rv streamed evict-first)

#define L_SEQ 512
#define D_DIM 64
#define H_HEADS 8

__device__ float g_s1[(size_t)H_HEADS * L_SEQ * L_SEQ];   // 8.4 MB scratch

__device__ __forceinline__ unsigned long long pack2(float lo, float hi) {
    unsigned long long r;
    asm("mov.b64 %0, {%1, %2};" : "=l"(r) : "f"(lo), "f"(hi));
    return r;
}
__device__ __forceinline__ void unpack2(unsigned long long p, float& lo, float& hi) {
    asm("mov.b64 {%0, %1}, %2;" : "=f"(lo), "=f"(hi) : "l"(p));
}
__device__ __forceinline__ void fma2(unsigned long long& d,
                                     unsigned long long a, unsigned long long b) {
    asm("fma.rn.f32x2 %0, %1, %2, %0;" : "+l"(d) : "l"(a), "l"(b));
}

// ---------------- Kernel A: S1 = Q K^T (FFMA2) ----------------
// Output tile 64(i) x 64(j), K=64, 4x4 microtile, packed-pair accumulators.
__global__ __launch_bounds__(256)
void qk_kernel(const float* __restrict__ q, const float* __restrict__ k)
{
    const int jt = blockIdx.x;            // 8
    const int it = blockIdx.y;            // 8
    const int h  = blockIdx.z;            // 8
    const int i0 = it << 6, j0 = jt << 6;
    __shared__ float sqT[64][68];         // [kk][i-local], float4 reads 16B-aligned
    __shared__ float skT[64][68];         // [kk][j-local]
    const int tid = threadIdx.x;

    // load q tile 64x64 and k tile 64x64, store transposed
    for (int idx = tid; idx < 64 * 16; idx += 256) {
        const int row = idx >> 4, c4 = (idx & 15) << 2;
        const float4 a = *reinterpret_cast<const float4*>(
            q + ((size_t)h * L_SEQ + i0 + row) * D_DIM + c4);
        sqT[c4 + 0][row] = a.x; sqT[c4 + 1][row] = a.y;
        sqT[c4 + 2][row] = a.z; sqT[c4 + 3][row] = a.w;
        const float4 b = *reinterpret_cast<const float4*>(
            k + ((size_t)h * L_SEQ + j0 + row) * D_DIM + c4);
        skT[c4 + 0][row] = b.x; skT[c4 + 1][row] = b.y;
        skT[c4 + 2][row] = b.z; skT[c4 + 3][row] = b.w;
    }
    __syncthreads();

    const int ty = tid >> 4, tx = tid & 15;   // 16 x 16 threads, 4x4 outputs each
    unsigned long long acc01[4] = {0ull, 0ull, 0ull, 0ull};   // cols (c0,c1) per row r
    unsigned long long acc23[4] = {0ull, 0ull, 0ull, 0ull};   // cols (c2,c3) per row r

    #pragma unroll 8
    for (int kk = 0; kk < 64; ++kk) {
        const float4 av = *reinterpret_cast<const float4*>(&sqT[kk][4 * ty]);
        const float4 bv = *reinterpret_cast<const float4*>(&skT[kk][4 * tx]);
        const unsigned long long b01 = pack2(bv.x, bv.y);
        const unsigned long long b23 = pack2(bv.z, bv.w);
        const unsigned long long a0 = pack2(av.x, av.x);
        const unsigned long long a1 = pack2(av.y, av.y);
        const unsigned long long a2 = pack2(av.z, av.z);
        const unsigned long long a3 = pack2(av.w, av.w);
        fma2(acc01[0], a0, b01); fma2(acc23[0], a0, b23);
        fma2(acc01[1], a1, b01); fma2(acc23[1], a1, b23);
        fma2(acc01[2], a2, b01); fma2(acc23[2], a2, b23);
        fma2(acc01[3], a3, b01); fma2(acc23[3], a3, b23);
    }

    #pragma unroll
    for (int r = 0; r < 4; ++r) {
        float4 o;
        unpack2(acc01[r], o.x, o.y);
        unpack2(acc23[r], o.z, o.w);
        *reinterpret_cast<float4*>(
            g_s1 + ((size_t)h * L_SEQ + i0 + 4 * ty + r) * L_SEQ + j0 + 4 * tx) = o;
    }
}

// ---------------- Kernel B: relation stream + softmax + fused PV ----------------
__global__ __launch_bounds__(256)
void rel_attn_kernel(const float* __restrict__ q_g,
                     const float* __restrict__ v_g,
                     const float* __restrict__ rk_g,
                     const float* __restrict__ rv_g,
                     const int*   __restrict__ mask_g,
                     float* __restrict__ out_attn,
                     float* __restrict__ out_p)
{
    const int i    = blockIdx.x;
    const int h    = blockIdx.y;
    const int tid  = threadIdx.x;
    const int warp = tid >> 5;
    const int lane = tid & 31;
    const int half = lane >> 4;
    const int hl   = lane & 15;

    __shared__ float  s_score[L_SEQ];
    __shared__ float  s_s1[L_SEQ];
    __shared__ int    s_mask[L_SEQ];
    __shared__ float  s_red[8];
    __shared__ float4 s_acc[16][16];

    const float* q     = q_g  + ((size_t)h * L_SEQ + i) * D_DIM;
    const float* rk    = rk_g + (((size_t)h * L_SEQ + i) * L_SEQ) * D_DIM;
    const int*   mrow  = mask_g + (size_t)i * L_SEQ;          // broadcast over h (B=1)
    const float* s1row = g_s1 + ((size_t)h * L_SEQ + i) * L_SEQ;

    // Preload S1 row (L2-resident) + mask row, coalesced.
    s_s1[tid]         = s1row[tid];
    s_s1[tid + 256]   = s1row[tid + 256];
    s_mask[tid]       = mrow[tid];
    s_mask[tid + 256] = mrow[tid + 256];
    __syncthreads();

    // Phase 1: score[j] = (S1[j] + q . rk[i,j]) / 8, masked.
    const float4 q4 = *reinterpret_cast<const float4*>(q + 4 * hl);

    #pragma unroll 8
    for (int jj = 0; jj < 32; ++jj) {
        const int j = (warp << 6) + (jj << 1) + half;
        const float4 rr = __ldcs(reinterpret_cast<const float4*>(rk + (size_t)j * D_DIM + 4 * hl));
        float p = q4.x * rr.x + q4.y * rr.y + q4.z * rr.z + q4.w * rr.w;
        p += __shfl_xor_sync(0xffffffffu, p, 8);
        p += __shfl_xor_sync(0xffffffffu, p, 4);
        p += __shfl_xor_sync(0xffffffffu, p, 2);
        p += __shfl_xor_sync(0xffffffffu, p, 1);
        if (hl == 0) {
            float s = (s_s1[j] + p) * 0.125f;      // 1/sqrt(64)
            if (s_mask[j] == 0) s = -1e9f;
            s_score[j] = s;
        }
    }
    __syncthreads();

    // Phase 2: softmax over j (thread owns tid, tid+256).
    float v0 = s_score[tid];
    float v1 = s_score[tid + 256];

    float m = fmaxf(v0, v1);
    #pragma unroll
    for (int o = 16; o > 0; o >>= 1)
        m = fmaxf(m, __shfl_xor_sync(0xffffffffu, m, o));
    if (lane == 0) s_red[warp] = m;
    __syncthreads();
    if (tid == 0) {
        float mm = s_red[0];
        #pragma unroll
        for (int w = 1; w < 8; ++w) mm = fmaxf(mm, s_red[w]);
        s_red[0] = mm;
    }
    __syncthreads();
    m = s_red[0];
    __syncthreads();

    const float e0 = __expf(v0 - m);
    const float e1 = __expf(v1 - m);
    float ssum = e0 + e1;
    #pragma unroll
    for (int o = 16; o > 0; o >>= 1)
        ssum += __shfl_xor_sync(0xffffffffu, ssum, o);
    if (lane == 0) s_red[warp] = ssum;
    __syncthreads();
    if (tid == 0) {
        float tot = s_red[0];
        #pragma unroll
        for (int w = 1; w < 8; ++w) tot += s_red[w];
        s_red[0] = tot;
    }
    __syncthreads();
    const float inv = 1.0f / s_red[0];

    const float p0 = e0 * inv;
    const float p1 = e1 * inv;
    s_score[tid]       = p0;
    s_score[tid + 256] = p1;

    // p_attn written once, never re-read: streaming stores keep L2 for v/s1.
    const size_t pbase = ((size_t)h * L_SEQ + i) * L_SEQ;
    __stcs(&out_p[pbase + tid], p0);
    __stcs(&out_p[pbase + tid + 256], p1);
    __syncthreads();

    // Phase 3: out_i[d] = sum_j p[j] * (v[j,d] + rv[i,j,d]).
    // v via default caching (head-major bid order keeps it hot), rv evict-first.
    const int gid = (warp << 1) + half;
    const float* vrow = v_g  + (size_t)h * L_SEQ * D_DIM;
    const float* rv   = rv_g + (((size_t)h * L_SEQ + i) * L_SEQ) * D_DIM;

    float4 acc = make_float4(0.f, 0.f, 0.f, 0.f);
    #pragma unroll 4
    for (int j = gid; j < L_SEQ; j += 16) {
        const float  pj  = s_score[j];
        const size_t off = (size_t)j * D_DIM + 4 * hl;
        const float4 vv  = *reinterpret_cast<const float4*>(vrow + off);
        const float4 rr  = __ldcs(reinterpret_cast<const float4*>(rv + off));
        acc.x += pj * (vv.x + rr.x);
        acc.y += pj * (vv.y + rr.y);
        acc.z += pj * (vv.z + rr.z);
        acc.w += pj * (vv.w + rr.w);
    }
    s_acc[gid][hl] = acc;
    __syncthreads();

    if (tid < 16) {
        float4 r = make_float4(0.f, 0.f, 0.f, 0.f);
        #pragma unroll
        for (int gg = 0; gg < 16; ++gg) {
            const float4 a = s_acc[gg][tid];
            r.x += a.x; r.y += a.y; r.z += a.z; r.w += a.w;
        }
        float4* oa = reinterpret_cast<float4*>(out_attn + ((size_t)h * L_SEQ + i) * D_DIM);
        oa[tid] = r;
    }
}

extern "C" void kernel_launch(void* const* d_in, const int* in_sizes, int n_in,
                              void* d_out, int out_size)
{
    const float* q    = (const float*)d_in[0];
    const float* k    = (const float*)d_in[1];
    const float* v    = (const float*)d_in[2];
    const float* rk   = (const float*)d_in[3];
    const float* rv   = (const float*)d_in[4];
    const int*   mask = (const int*)  d_in[5];

    float* out      = (float*)d_out;
    float* out_attn = out;                                        // [1,8,512,64]
    float* out_p    = out + (size_t)H_HEADS * L_SEQ * D_DIM;      // [1,8,512,512]

    qk_kernel<<<dim3(8, 8, 8), 256>>>(q, k);
    rel_attn_kernel<<<dim3(L_SEQ, H_HEADS), 256>>>(q, v, rk, rv, mask, out_attn, out_p);
}